// round 9
// baseline (speedup 1.0000x reference)
#include <cuda_runtime.h>
#include <math_constants.h>

#define IN_DIM 128
#define OUT_DIM 64
#define MAX_N 50000
#define MAX_E 800000
#define ALPHA_LEAKY 0.2f
#define EPS_F 1e-10f

#define SCAN_CHUNK 1024

// ---- scratch (device globals; no allocation allowed) ----
__device__ float  g_h[(size_t)MAX_N * OUT_DIM];   // 12.8 MB
__device__ float  g_ssrc[MAX_N];
__device__ float  g_stgt[MAX_N];
__device__ float  g_ws[IN_DIM];                   // W^T a[:64]
__device__ float  g_wt[IN_DIM];                   // W^T a[64:]
__device__ int    g_deg[MAX_N];
__device__ int    g_rowptr[MAX_N + 1];
__device__ int    g_cursor[MAX_N];
__device__ int    g_bsum[(MAX_N + SCAN_CHUNK - 1) / SCAN_CHUNK];
__device__ float2 g_pack[MAX_E];                  // (leaky score, src-as-float-bits)

// ---------------------------------------------------------------------------
// wv: w_s[k] = sum_o W[o][k] * a[o];  w_t[k] = sum_o W[o][k] * a[64+o]
// ---------------------------------------------------------------------------
__global__ void wv_kernel(const float* __restrict__ Wg, const float* __restrict__ a) {
    int k = threadIdx.x;    // 0..127
    float ws = 0.f, wt = 0.f;
#pragma unroll 8
    for (int o = 0; o < OUT_DIM; o++) {
        float w = __ldg(Wg + o * IN_DIM + k);
        ws = fmaf(w, __ldg(a + o), ws);
        wt = fmaf(w, __ldg(a + OUT_DIM + o), wt);
    }
    g_ws[k] = ws;
    g_wt[k] = wt;
}

// ---------------------------------------------------------------------------
// score: s_src[n] = X[n].w_s ; s_tgt[n] = X[n].w_t  (warp per node)
// ---------------------------------------------------------------------------
__global__ void __launch_bounds__(256) score_kernel(const float* __restrict__ X, int N) {
    int gw   = (blockIdx.x * blockDim.x + threadIdx.x) >> 5;
    int lane = threadIdx.x & 31;
    if (gw >= N) return;
    float4 x4 = ((const float4*)(X + (size_t)gw * IN_DIM))[lane];
    float4 s4 = ((const float4*)g_ws)[lane];
    float4 t4 = ((const float4*)g_wt)[lane];
    float ss = x4.x*s4.x + x4.y*s4.y + x4.z*s4.z + x4.w*s4.w;
    float st = x4.x*t4.x + x4.y*t4.y + x4.z*t4.z + x4.w*t4.w;
#pragma unroll
    for (int off = 16; off > 0; off >>= 1) {
        ss += __shfl_xor_sync(0xffffffffu, ss, off);
        st += __shfl_xor_sync(0xffffffffu, st, off);
    }
    if (lane == 0) {
        g_ssrc[gw] = ss;
        g_stgt[gw] = st;
    }
}

// ---------------------------------------------------------------------------
// histogram of targets
// ---------------------------------------------------------------------------
__global__ void hist_kernel(const int* __restrict__ ei, int E) {
    int i = blockIdx.x * blockDim.x + threadIdx.x;
    if (i >= E) return;
    atomicAdd(&g_deg[__ldg(ei + E + i)], 1);
}

// ---------------------------------------------------------------------------
// exclusive scan, 3 phases (chunk=1024)
// ---------------------------------------------------------------------------
__global__ void __launch_bounds__(SCAN_CHUNK) scan1_kernel(int n) {
    __shared__ int wsum[32];
    int t = threadIdx.x, b = blockIdx.x;
    int gi = b * SCAN_CHUNK + t;
    int lane = t & 31, w = t >> 5;
    int v = (gi < n) ? g_deg[gi] : 0;
    int x = v;
#pragma unroll
    for (int off = 1; off < 32; off <<= 1) {
        int y = __shfl_up_sync(0xffffffffu, x, off);
        if (lane >= off) x += y;
    }
    if (lane == 31) wsum[w] = x;
    __syncthreads();
    if (w == 0) {
        int s = wsum[lane];
#pragma unroll
        for (int off = 1; off < 32; off <<= 1) {
            int y = __shfl_up_sync(0xffffffffu, s, off);
            if (lane >= off) s += y;
        }
        wsum[lane] = s;
    }
    __syncthreads();
    int incl = x + ((w > 0) ? wsum[w - 1] : 0);
    if (gi < n) g_rowptr[gi] = incl - v;
    if (t == SCAN_CHUNK - 1) g_bsum[b] = incl;
}

__global__ void __launch_bounds__(SCAN_CHUNK) scan2_kernel(int nb) {
    __shared__ int wsum[32];
    int t = threadIdx.x;
    int lane = t & 31, w = t >> 5;
    int v = (t < nb) ? g_bsum[t] : 0;
    int x = v;
#pragma unroll
    for (int off = 1; off < 32; off <<= 1) {
        int y = __shfl_up_sync(0xffffffffu, x, off);
        if (lane >= off) x += y;
    }
    if (lane == 31) wsum[w] = x;
    __syncthreads();
    if (w == 0) {
        int s = wsum[lane];
#pragma unroll
        for (int off = 1; off < 32; off <<= 1) {
            int y = __shfl_up_sync(0xffffffffu, s, off);
            if (lane >= off) s += y;
        }
        wsum[lane] = s;
    }
    __syncthreads();
    int incl = x + ((w > 0) ? wsum[w - 1] : 0);
    if (t < nb) g_bsum[t] = incl - v;
}

__global__ void scan3_kernel(int n, int E) {
    int gi = blockIdx.x * blockDim.x + threadIdx.x;
    if (gi < n) {
        int r = g_rowptr[gi] + g_bsum[gi >> 10];
        g_rowptr[gi] = r;
        g_cursor[gi] = r;
    }
    if (gi == 0) g_rowptr[n] = E;
}

// ---------------------------------------------------------------------------
// GEMM: g_h[n][o] = sum_k X[n][k] * W[o][k]
// 64 nodes x 64 outs per block, 256 threads, 4x4 register tile per thread.
// ---------------------------------------------------------------------------
#define WT_PITCH (OUT_DIM + 4)   // 68
#define XS_PITCH (IN_DIM + 4)    // 132
#define GEMM_SMEM_BYTES ((IN_DIM * WT_PITCH + 64 * XS_PITCH) * (int)sizeof(float))

__global__ void __launch_bounds__(256) gemm_kernel(
    const float* __restrict__ X, const float* __restrict__ Wg, int N)
{
    extern __shared__ float sm[];
    float* Wt = sm;                              // [IN_DIM][WT_PITCH]
    float* Xs = sm + IN_DIM * WT_PITCH;          // [64][XS_PITCH]

    int t = threadIdx.x;

    for (int i = t; i < IN_DIM * OUT_DIM; i += 256) {
        int o = i >> 7;
        int k = i & 127;
        Wt[k * WT_PITCH + o] = Wg[i];
    }

    int n0 = blockIdx.x * 64;
    for (int i = t; i < 64 * 32; i += 256) {
        int n  = i >> 5;
        int kq = i & 31;
        int gn = n0 + n;
        float4 v = make_float4(0.f, 0.f, 0.f, 0.f);
        if (gn < N) v = ((const float4*)(X + (size_t)gn * IN_DIM))[kq];
        ((float4*)(Xs + n * XS_PITCH))[kq] = v;
    }
    __syncthreads();

    int oq = (t & 15);
    int nq = (t >> 4) * 4;

    float acc[4][4];
#pragma unroll
    for (int j = 0; j < 4; j++)
#pragma unroll
        for (int c = 0; c < 4; c++) acc[j][c] = 0.0f;

#pragma unroll 8
    for (int k = 0; k < IN_DIM; k++) {
        float4 w4 = ((const float4*)(Wt + k * WT_PITCH))[oq];
#pragma unroll
        for (int j = 0; j < 4; j++) {
            float x = Xs[(nq + j) * XS_PITCH + k];
            acc[j][0] = fmaf(x, w4.x, acc[j][0]);
            acc[j][1] = fmaf(x, w4.y, acc[j][1]);
            acc[j][2] = fmaf(x, w4.z, acc[j][2]);
            acc[j][3] = fmaf(x, w4.w, acc[j][3]);
        }
    }

#pragma unroll
    for (int j = 0; j < 4; j++) {
        int gn = n0 + nq + j;
        if (gn < N) {
            float4 v = make_float4(acc[j][0], acc[j][1], acc[j][2], acc[j][3]);
            ((float4*)(g_h + (size_t)gn * OUT_DIM))[oq] = v;
        }
    }
}

// ---------------------------------------------------------------------------
// CSR fill: compute leaky score, place (e, src) at cursor slot of its target
// ---------------------------------------------------------------------------
__global__ void fill_kernel(const int* __restrict__ ei, int E) {
    int i = blockIdx.x * blockDim.x + threadIdx.x;
    if (i >= E) return;
    int src = __ldg(ei + i);
    int tgt = __ldg(ei + E + i);
    float e = g_ssrc[src] + g_stgt[tgt];
    e = (e > 0.0f) ? e : (ALPHA_LEAKY * e);
    int pos = atomicAdd(&g_cursor[tgt], 1);
    g_pack[pos] = make_float2(e, __int_as_float(src));
}

// ---------------------------------------------------------------------------
// aggregate: warp per target, 2 edges per inner iteration.
// Lanes 0-15 process edge k (float4 over 64 dims), lanes 16-31 edge k+1.
// Halves combined with shfl_xor(16); 16-lane float4 store with fused ELU.
// ---------------------------------------------------------------------------
__global__ void __launch_bounds__(256) agg_kernel(float* __restrict__ out, int N) {
    int gw   = (blockIdx.x * blockDim.x + threadIdx.x) >> 5;
    int lane = threadIdx.x & 31;
    if (gw >= N) return;

    int beg = g_rowptr[gw];
    int end = g_rowptr[gw + 1];

    // phase 1: segment max and exp-sum
    float m = -CUDART_INF_F;
    for (int j = beg + lane; j < end; j += 32)
        m = fmaxf(m, g_pack[j].x);
#pragma unroll
    for (int off = 16; off > 0; off >>= 1)
        m = fmaxf(m, __shfl_xor_sync(0xffffffffu, m, off));

    float s = 0.0f;
    for (int j = beg + lane; j < end; j += 32)
        s += __expf(g_pack[j].x - m);
#pragma unroll
    for (int off = 16; off > 0; off >>= 1)
        s += __shfl_xor_sync(0xffffffffu, s, off);

    float inv = 1.0f / (s + EPS_F);

    int half = lane >> 4;      // 0 or 1
    int qi   = lane & 15;      // float4 index within 64-dim row

    float4 acc = make_float4(0.f, 0.f, 0.f, 0.f);
    for (int base = beg; base < end; base += 32) {
        int j = base + lane;
        float att = 0.0f;
        int   src = 0;
        if (j < end) {
            float2 p = g_pack[j];
            att = __expf(p.x - m) * inv;
            src = __float_as_int(p.y);
        }
        int cnt = min(32, end - base);
#pragma unroll 2
        for (int k = 0; k < cnt; k += 2) {
            int kk = k + half;
            float a  = __shfl_sync(0xffffffffu, att, kk < cnt ? kk : k);
            int   sk = __shfl_sync(0xffffffffu, src, kk < cnt ? kk : k);
            if (kk >= cnt) a = 0.0f;
            float4 hv = ((const float4*)(g_h + (size_t)sk * OUT_DIM))[qi];
            acc.x = fmaf(a, hv.x, acc.x);
            acc.y = fmaf(a, hv.y, acc.y);
            acc.z = fmaf(a, hv.z, acc.z);
            acc.w = fmaf(a, hv.w, acc.w);
        }
    }

    // combine the two halves
    acc.x += __shfl_xor_sync(0xffffffffu, acc.x, 16);
    acc.y += __shfl_xor_sync(0xffffffffu, acc.y, 16);
    acc.z += __shfl_xor_sync(0xffffffffu, acc.z, 16);
    acc.w += __shfl_xor_sync(0xffffffffu, acc.w, 16);

    if (half == 0) {
        float4 o;
        o.x = (acc.x > 0.0f) ? acc.x : expm1f(acc.x);
        o.y = (acc.y > 0.0f) ? acc.y : expm1f(acc.y);
        o.z = (acc.z > 0.0f) ? acc.z : expm1f(acc.z);
        o.w = (acc.w > 0.0f) ? acc.w : expm1f(acc.w);
        ((float4*)(out + (size_t)gw * OUT_DIM))[qi] = o;
    }
}

extern "C" void kernel_launch(void* const* d_in, const int* in_sizes, int n_in,
                              void* d_out, int out_size) {
    const float* X   = (const float*)d_in[0];
    const int*   EI  = (const int*)d_in[1];      // int32 edge_index [2, E]
    const float* Wg  = (const float*)d_in[2];
    const float* A   = (const float*)d_in[3];
    float*       out = (float*)d_out;

    int N = in_sizes[0] / IN_DIM;   // 50000
    int E = in_sizes[1] / 2;        // 800000
    int nb = (N + SCAN_CHUNK - 1) / SCAN_CHUNK;

    // one-time host-side resources (no device memory allocated)
    static cudaStream_t s2 = nullptr, s3 = nullptr;
    static cudaEvent_t  e0 = nullptr, e2 = nullptr, e3 = nullptr;
    static void* deg_ptr = nullptr;
    if (s2 == nullptr) {
        cudaStreamCreateWithFlags(&s2, cudaStreamNonBlocking);
        cudaStreamCreateWithFlags(&s3, cudaStreamNonBlocking);
        cudaEventCreateWithFlags(&e0, cudaEventDisableTiming);
        cudaEventCreateWithFlags(&e2, cudaEventDisableTiming);
        cudaEventCreateWithFlags(&e3, cudaEventDisableTiming);
        cudaGetSymbolAddress(&deg_ptr, g_deg);
        cudaFuncSetAttribute(gemm_kernel,
                             cudaFuncAttributeMaxDynamicSharedMemorySize,
                             GEMM_SMEM_BYTES);
    }

    // fork
    cudaEventRecord(e0, (cudaStream_t)0);
    cudaStreamWaitEvent(s2, e0, 0);
    cudaStreamWaitEvent(s3, e0, 0);

    // chain B (s3): scores directly from X (independent of GEMM)
    wv_kernel<<<1, IN_DIM, 0, s3>>>(Wg, A);
    score_kernel<<<(unsigned)(((size_t)N * 32 + 255) / 256), 256, 0, s3>>>(X, N);
    cudaEventRecord(e3, s3);

    // chain A (s2): CSR build, then fill (needs scores from B)
    cudaMemsetAsync(deg_ptr, 0, (size_t)N * sizeof(int), s2);
    hist_kernel<<<(E + 255) / 256, 256, 0, s2>>>(EI, E);
    scan1_kernel<<<nb, SCAN_CHUNK, 0, s2>>>(N);
    scan2_kernel<<<1, SCAN_CHUNK, 0, s2>>>(nb);
    scan3_kernel<<<(N + 255) / 256, 256, 0, s2>>>(N, E);
    cudaStreamWaitEvent(s2, e3, 0);
    fill_kernel<<<(E + 255) / 256, 256, 0, s2>>>(EI, E);
    cudaEventRecord(e2, s2);

    // main chain: GEMM concurrent with A and B
    gemm_kernel<<<(N + 63) / 64, 256, GEMM_SMEM_BYTES>>>(X, Wg, N);

    // join: agg needs h (main) + CSR pack (A)
    cudaStreamWaitEvent((cudaStream_t)0, e2, 0);
    agg_kernel<<<(unsigned)(((size_t)N * 32 + 255) / 256), 256>>>(out, N);
}

// round 10
// speedup vs baseline: 1.0260x; 1.0260x over previous
#include <cuda_runtime.h>
#include <math_constants.h>

#define IN_DIM 128
#define OUT_DIM 64
#define MAX_N 50000
#define MAX_E 800000
#define ALPHA_LEAKY 0.2f
#define EPS_F 1e-10f

#define SCAN_CHUNK 1024

// ---- scratch (device globals; no allocation allowed) ----
__device__ float  g_h[(size_t)MAX_N * OUT_DIM];   // 12.8 MB
__device__ float  g_ssrc[MAX_N];
__device__ float  g_stgt[MAX_N];
__device__ float  g_ws[IN_DIM];                   // W^T a[:64]
__device__ float  g_wt[IN_DIM];                   // W^T a[64:]
__device__ int    g_deg[MAX_N];
__device__ int    g_rowptr[MAX_N + 1];
__device__ int    g_cursor[MAX_N];
__device__ int    g_bsum[(MAX_N + SCAN_CHUNK - 1) / SCAN_CHUNK];
__device__ float2 g_pack[MAX_E];                  // (exp(leaky score), src-as-float-bits)

// ---------------------------------------------------------------------------
// wv: w_s[k] = sum_o W[o][k]*a[o];  w_t[k] = sum_o W[o][k]*a[64+o]
// ---------------------------------------------------------------------------
__global__ void wv_kernel(const float* __restrict__ Wg, const float* __restrict__ a) {
    int k = threadIdx.x;    // 0..127
    float ws = 0.f, wt = 0.f;
#pragma unroll 8
    for (int o = 0; o < OUT_DIM; o++) {
        float w = __ldg(Wg + o * IN_DIM + k);
        ws = fmaf(w, __ldg(a + o), ws);
        wt = fmaf(w, __ldg(a + OUT_DIM + o), wt);
    }
    g_ws[k] = ws;
    g_wt[k] = wt;
}

// ---------------------------------------------------------------------------
// score: s_src[n] = X[n].w_s ; s_tgt[n] = X[n].w_t  (warp per node)
// Runs BEFORE gemm on main stream; also pre-warms X into L2 for the GEMM.
// ---------------------------------------------------------------------------
__global__ void __launch_bounds__(256) score_kernel(const float* __restrict__ X, int N) {
    int gw   = (blockIdx.x * blockDim.x + threadIdx.x) >> 5;
    int lane = threadIdx.x & 31;
    if (gw >= N) return;
    float4 x4 = ((const float4*)(X + (size_t)gw * IN_DIM))[lane];
    float4 s4 = ((const float4*)g_ws)[lane];
    float4 t4 = ((const float4*)g_wt)[lane];
    float ss = x4.x*s4.x + x4.y*s4.y + x4.z*s4.z + x4.w*s4.w;
    float st = x4.x*t4.x + x4.y*t4.y + x4.z*t4.z + x4.w*t4.w;
#pragma unroll
    for (int off = 16; off > 0; off >>= 1) {
        ss += __shfl_xor_sync(0xffffffffu, ss, off);
        st += __shfl_xor_sync(0xffffffffu, st, off);
    }
    if (lane == 0) {
        g_ssrc[gw] = ss;
        g_stgt[gw] = st;
    }
}

// ---------------------------------------------------------------------------
// histogram of targets
// ---------------------------------------------------------------------------
__global__ void hist_kernel(const int* __restrict__ ei, int E) {
    int i = blockIdx.x * blockDim.x + threadIdx.x;
    if (i >= E) return;
    atomicAdd(&g_deg[__ldg(ei + E + i)], 1);
}

// ---------------------------------------------------------------------------
// exclusive scan, 3 phases (chunk=1024)  [side stream, hidden under main]
// ---------------------------------------------------------------------------
__global__ void __launch_bounds__(SCAN_CHUNK) scan1_kernel(int n) {
    __shared__ int wsum[32];
    int t = threadIdx.x, b = blockIdx.x;
    int gi = b * SCAN_CHUNK + t;
    int lane = t & 31, w = t >> 5;
    int v = (gi < n) ? g_deg[gi] : 0;
    int x = v;
#pragma unroll
    for (int off = 1; off < 32; off <<= 1) {
        int y = __shfl_up_sync(0xffffffffu, x, off);
        if (lane >= off) x += y;
    }
    if (lane == 31) wsum[w] = x;
    __syncthreads();
    if (w == 0) {
        int s = wsum[lane];
#pragma unroll
        for (int off = 1; off < 32; off <<= 1) {
            int y = __shfl_up_sync(0xffffffffu, s, off);
            if (lane >= off) s += y;
        }
        wsum[lane] = s;
    }
    __syncthreads();
    int incl = x + ((w > 0) ? wsum[w - 1] : 0);
    if (gi < n) g_rowptr[gi] = incl - v;
    if (t == SCAN_CHUNK - 1) g_bsum[b] = incl;
}

__global__ void __launch_bounds__(SCAN_CHUNK) scan2_kernel(int nb) {
    __shared__ int wsum[32];
    int t = threadIdx.x;
    int lane = t & 31, w = t >> 5;
    int v = (t < nb) ? g_bsum[t] : 0;
    int x = v;
#pragma unroll
    for (int off = 1; off < 32; off <<= 1) {
        int y = __shfl_up_sync(0xffffffffu, x, off);
        if (lane >= off) x += y;
    }
    if (lane == 31) wsum[w] = x;
    __syncthreads();
    if (w == 0) {
        int s = wsum[lane];
#pragma unroll
        for (int off = 1; off < 32; off <<= 1) {
            int y = __shfl_up_sync(0xffffffffu, s, off);
            if (lane >= off) s += y;
        }
        wsum[lane] = s;
    }
    __syncthreads();
    int incl = x + ((w > 0) ? wsum[w - 1] : 0);
    if (t < nb) g_bsum[t] = incl - v;
}

__global__ void scan3_kernel(int n, int E) {
    int gi = blockIdx.x * blockDim.x + threadIdx.x;
    if (gi < n) {
        int r = g_rowptr[gi] + g_bsum[gi >> 10];
        g_rowptr[gi] = r;
        g_cursor[gi] = r;
    }
    if (gi == 0) g_rowptr[n] = E;
}

// ---------------------------------------------------------------------------
// GEMM: g_h[n][o] = sum_k X[n][k] * W[o][k]
// 64 nodes x 64 outs per block, 256 threads, 4x4 register tile per thread.
// ---------------------------------------------------------------------------
#define WT_PITCH (OUT_DIM + 4)   // 68
#define XS_PITCH (IN_DIM + 4)    // 132
#define GEMM_SMEM_BYTES ((IN_DIM * WT_PITCH + 64 * XS_PITCH) * (int)sizeof(float))

__global__ void __launch_bounds__(256) gemm_kernel(
    const float* __restrict__ X, const float* __restrict__ Wg, int N)
{
    extern __shared__ float sm[];
    float* Wt = sm;                              // [IN_DIM][WT_PITCH]
    float* Xs = sm + IN_DIM * WT_PITCH;          // [64][XS_PITCH]

    int t = threadIdx.x;

    for (int i = t; i < IN_DIM * OUT_DIM; i += 256) {
        int o = i >> 7;
        int k = i & 127;
        Wt[k * WT_PITCH + o] = Wg[i];
    }

    int n0 = blockIdx.x * 64;
    for (int i = t; i < 64 * 32; i += 256) {
        int n  = i >> 5;
        int kq = i & 31;
        int gn = n0 + n;
        float4 v = make_float4(0.f, 0.f, 0.f, 0.f);
        if (gn < N) v = ((const float4*)(X + (size_t)gn * IN_DIM))[kq];
        ((float4*)(Xs + n * XS_PITCH))[kq] = v;
    }
    __syncthreads();

    int oq = (t & 15);
    int nq = (t >> 4) * 4;

    float acc[4][4];
#pragma unroll
    for (int j = 0; j < 4; j++)
#pragma unroll
        for (int c = 0; c < 4; c++) acc[j][c] = 0.0f;

#pragma unroll 8
    for (int k = 0; k < IN_DIM; k++) {
        float4 w4 = ((const float4*)(Wt + k * WT_PITCH))[oq];
#pragma unroll
        for (int j = 0; j < 4; j++) {
            float x = Xs[(nq + j) * XS_PITCH + k];
            acc[j][0] = fmaf(x, w4.x, acc[j][0]);
            acc[j][1] = fmaf(x, w4.y, acc[j][1]);
            acc[j][2] = fmaf(x, w4.z, acc[j][2]);
            acc[j][3] = fmaf(x, w4.w, acc[j][3]);
        }
    }

#pragma unroll
    for (int j = 0; j < 4; j++) {
        int gn = n0 + nq + j;
        if (gn < N) {
            float4 v = make_float4(acc[j][0], acc[j][1], acc[j][2], acc[j][3]);
            ((float4*)(g_h + (size_t)gn * OUT_DIM))[oq] = v;
        }
    }
}

// ---------------------------------------------------------------------------
// CSR fill: e = leaky(s_src+s_tgt); store (exp(e), src) at cursor slot.
// Max-free softmax is safe: |e| <~ 20, exp fits fp32 comfortably, and the
// normalization exp(e)/sum(exp(e)) is algebraically identical to the
// max-subtracted form (EPS term differs by <=1e-10 relative).
// ---------------------------------------------------------------------------
__global__ void fill_kernel(const int* __restrict__ ei, int E) {
    int i = blockIdx.x * blockDim.x + threadIdx.x;
    if (i >= E) return;
    int src = __ldg(ei + i);
    int tgt = __ldg(ei + E + i);
    float e = g_ssrc[src] + g_stgt[tgt];
    e = (e > 0.0f) ? e : (ALPHA_LEAKY * e);
    float ex = __expf(e);
    int pos = atomicAdd(&g_cursor[tgt], 1);
    g_pack[pos] = make_float2(ex, __int_as_float(src));
}

// ---------------------------------------------------------------------------
// aggregate: one warp per target, SINGLE pass over its CSR segment.
// acc_lane += ex_k * h[src_k][lane-pair]; S += ex_k (identical on all lanes
// via broadcast -> no reductions). Finally out = ELU(acc/(S+EPS)).
// ---------------------------------------------------------------------------
__global__ void __launch_bounds__(256) agg_kernel(float* __restrict__ out, int N) {
    int gw   = (blockIdx.x * blockDim.x + threadIdx.x) >> 5;
    int lane = threadIdx.x & 31;
    if (gw >= N) return;

    int beg = g_rowptr[gw];
    int end = g_rowptr[gw + 1];

    float  S   = 0.0f;
    float2 acc = make_float2(0.0f, 0.0f);

    for (int base = beg; base < end; base += 32) {
        int j = base + lane;
        float ex = 0.0f;
        int   src = 0;
        if (j < end) {
            float2 p = __ldg(&g_pack[j]);
            ex  = p.x;
            src = __float_as_int(p.y);
        }
        int cnt = min(32, end - base);
        for (int k = 0; k < cnt; k++) {
            float a  = __shfl_sync(0xffffffffu, ex, k);
            int   sk = __shfl_sync(0xffffffffu, src, k);
            S += a;
            float2 hv = __ldg((const float2*)(g_h + (size_t)sk * OUT_DIM) + lane);
            acc.x = fmaf(a, hv.x, acc.x);
            acc.y = fmaf(a, hv.y, acc.y);
        }
    }

    float inv = 1.0f / (S + EPS_F);
    float2 o;
    o.x = acc.x * inv;
    o.y = acc.y * inv;
    o.x = (o.x > 0.0f) ? o.x : expm1f(o.x);
    o.y = (o.y > 0.0f) ? o.y : expm1f(o.y);
    ((float2*)(out + (size_t)gw * OUT_DIM))[lane] = o;
}

extern "C" void kernel_launch(void* const* d_in, const int* in_sizes, int n_in,
                              void* d_out, int out_size) {
    const float* X   = (const float*)d_in[0];
    const int*   EI  = (const int*)d_in[1];      // int32 edge_index [2, E]
    const float* Wg  = (const float*)d_in[2];
    const float* A   = (const float*)d_in[3];
    float*       out = (float*)d_out;

    int N = in_sizes[0] / IN_DIM;   // 50000
    int E = in_sizes[1] / 2;        // 800000
    int nb = (N + SCAN_CHUNK - 1) / SCAN_CHUNK;

    // one-time host-side resources (no device memory allocated)
    static cudaStream_t s2 = nullptr;
    static cudaEvent_t  e0 = nullptr, eScore = nullptr, eFill = nullptr;
    static void* deg_ptr = nullptr;
    if (s2 == nullptr) {
        cudaStreamCreateWithFlags(&s2, cudaStreamNonBlocking);
        cudaEventCreateWithFlags(&e0, cudaEventDisableTiming);
        cudaEventCreateWithFlags(&eScore, cudaEventDisableTiming);
        cudaEventCreateWithFlags(&eFill, cudaEventDisableTiming);
        cudaGetSymbolAddress(&deg_ptr, g_deg);
        cudaFuncSetAttribute(gemm_kernel,
                             cudaFuncAttributeMaxDynamicSharedMemorySize,
                             GEMM_SMEM_BYTES);
    }

    // fork
    cudaEventRecord(e0, (cudaStream_t)0);
    cudaStreamWaitEvent(s2, e0, 0);

    // main: scores first (cheap; also pre-warms X into L2), then GEMM
    wv_kernel<<<1, IN_DIM>>>(Wg, A);
    score_kernel<<<(unsigned)(((size_t)N * 32 + 255) / 256), 256>>>(X, N);
    cudaEventRecord(eScore, (cudaStream_t)0);
    gemm_kernel<<<(N + 63) / 64, 256, GEMM_SMEM_BYTES>>>(X, Wg, N);

    // side: CSR build, then fill (needs scores only) -- overlaps with GEMM
    cudaMemsetAsync(deg_ptr, 0, (size_t)N * sizeof(int), s2);
    hist_kernel<<<(E + 255) / 256, 256, 0, s2>>>(EI, E);
    scan1_kernel<<<nb, SCAN_CHUNK, 0, s2>>>(N);
    scan2_kernel<<<1, SCAN_CHUNK, 0, s2>>>(nb);
    scan3_kernel<<<(N + 255) / 256, 256, 0, s2>>>(N, E);
    cudaStreamWaitEvent(s2, eScore, 0);
    fill_kernel<<<(E + 255) / 256, 256, 0, s2>>>(EI, E);
    cudaEventRecord(eFill, s2);

    // join: agg needs h (main, in-order) + pack (side)
    cudaStreamWaitEvent((cudaStream_t)0, eFill, 0);
    agg_kernel<<<(unsigned)(((size_t)N * 32 + 255) / 256), 256>>>(out, N);
}